// round 1
// baseline (speedup 1.0000x reference)
#include <cuda_runtime.h>

#define Nn 16
#define Cc 64
#define Hh 256
#define Ww 256
#define HW 65536
#define NHW 1048576

// ---------------- scratch (static device globals; no allocation) ----------------
__device__ float g_h[NHW];         // conv1 output (1 channel)
__device__ float g_fz[NHW];        // fuzzify output
__device__ float g_part1[512 * 2]; // K1 partial (sum, sumsq)
__device__ float g_bn1AB[2];       // fused BN1 scale/shift
__device__ float g_part2[256 * 54];// K4 partial (v[9], M[45])
__device__ float g_Wf[64 * 10];    // fused conv2 weights (9) + bias (1) per channel

// ---------------- helpers ----------------
__device__ __forceinline__ unsigned smem_u32(const void* p) {
    unsigned r;
    asm("{ .reg .u64 t; cvta.to.shared.u64 t, %1; cvt.u32.u64 %0, t; }" : "=r"(r) : "l"(p));
    return r;
}
__device__ __forceinline__ void cp16(unsigned dst, const void* src) {
    asm volatile("cp.async.cg.shared.global [%0], [%1], 16;\n" :: "r"(dst), "l"(src));
}
__device__ __forceinline__ void cp_commit() {
    asm volatile("cp.async.commit_group;\n");
}

// ================= K1: conv1 (64ch -> 1ch, 3x3 SAME) + BN1 partial sums =========
// grid (32 rowgroups of 8, 16 n), 128 threads, 2 output cols per thread.
#define T1_ROWS 10
#define T1_PITCH 264   // floats; data col w at idx w+4 (16B aligned base for cp.async)

__device__ __forceinline__ void k1_issue(const float* xc, int rg, int tid,
                                         float (*buf)[T1_PITCH]) {
    #pragma unroll
    for (int k = 0; k < 5; ++k) {            // 10 rows * 64 float4 = 640 = 5*128
        int i  = tid + k * 128;
        int r  = i >> 6;
        int c4 = i & 63;
        int gr = rg * 8 - 1 + r;
        if (gr >= 0 && gr < Hh) {
            unsigned dst = smem_u32(&buf[r][4 + c4 * 4]);
            cp16(dst, xc + gr * Ww + c4 * 4);
        }
    }
}

__global__ __launch_bounds__(128) void k1_conv1(const float* __restrict__ x,
                                                const float* __restrict__ w1,
                                                const float* __restrict__ b1) {
    __shared__ float sw[576];
    __shared__ float tile[2][T1_ROWS][T1_PITCH];
    const int tid = threadIdx.x;
    const int rg = blockIdx.x, n = blockIdx.y;

    float* sp = &tile[0][0][0];
    for (int i = tid; i < 2 * T1_ROWS * T1_PITCH; i += 128) sp[i] = 0.f;
    for (int i = tid; i < 576; i += 128) sw[i] = w1[i];
    __syncthreads();

    float a0[8], a1[8];
    #pragma unroll
    for (int i = 0; i < 8; ++i) { a0[i] = 0.f; a1[i] = 0.f; }

    const float* xn = x + (size_t)n * Cc * HW;

    k1_issue(xn, rg, tid, tile[0]);
    cp_commit();

    for (int c = 0; c < 64; ++c) {
        if (c < 63) {
            k1_issue(xn + (size_t)(c + 1) * HW, rg, tid, tile[(c + 1) & 1]);
            cp_commit();
            asm volatile("cp.async.wait_group 1;\n");
        } else {
            asm volatile("cp.async.wait_group 0;\n");
        }
        __syncthreads();

        float wv[9];
        #pragma unroll
        for (int j = 0; j < 9; ++j) wv[j] = sw[c * 9 + j];

        const float (*sm)[T1_PITCH] = tile[c & 1];
        #pragma unroll
        for (int r = 0; r < T1_ROWS; ++r) {
            float  vm = sm[r][3 + 2 * tid];
            float2 vp = *(const float2*)&sm[r][4 + 2 * tid];
            float  vq = sm[r][6 + 2 * tid];
            #pragma unroll
            for (int kh = 0; kh < 3; ++kh) {
                int o = r - kh;
                if (o >= 0 && o < 8) {
                    a0[o] = fmaf(wv[kh*3+0], vm,   fmaf(wv[kh*3+1], vp.x, fmaf(wv[kh*3+2], vp.y, a0[o])));
                    a1[o] = fmaf(wv[kh*3+0], vp.x, fmaf(wv[kh*3+1], vp.y, fmaf(wv[kh*3+2], vq,   a1[o])));
                }
            }
        }
        __syncthreads();
    }

    const float bb = __ldg(b1);
    float s = 0.f, s2 = 0.f;
    size_t obase = (size_t)n * HW + (size_t)(rg * 8) * Ww + 2 * tid;
    #pragma unroll
    for (int o = 0; o < 8; ++o) {
        float v0 = a0[o] + bb, v1 = a1[o] + bb;
        *(float2*)&g_h[obase + (size_t)o * Ww] = make_float2(v0, v1);
        s  += v0 + v1;
        s2 += v0 * v0 + v1 * v1;
    }
    #pragma unroll
    for (int off = 16; off; off >>= 1) {
        s  += __shfl_down_sync(0xffffffffu, s,  off);
        s2 += __shfl_down_sync(0xffffffffu, s2, off);
    }
    __shared__ float red[8];
    int wid = tid >> 5, lane = tid & 31;
    if (lane == 0) { red[wid] = s; red[4 + wid] = s2; }
    __syncthreads();
    if (tid == 0) {
        int bid = n * 32 + rg;
        g_part1[bid * 2 + 0] = red[0] + red[1] + red[2] + red[3];
        g_part1[bid * 2 + 1] = red[4] + red[5] + red[6] + red[7];
    }
}

// ================= K2: reduce BN1 partials -> fused scale/shift =================
__global__ __launch_bounds__(256) void k2_bn1(const float* __restrict__ g1,
                                              const float* __restrict__ be1) {
    __shared__ double sd[256], sd2[256];
    int tid = threadIdx.x;
    sd[tid]  = (double)g_part1[2 * tid + 0] + (double)g_part1[2 * (tid + 256) + 0];
    sd2[tid] = (double)g_part1[2 * tid + 1] + (double)g_part1[2 * (tid + 256) + 1];
    __syncthreads();
    for (int off = 128; off; off >>= 1) {
        if (tid < off) { sd[tid] += sd[tid + off]; sd2[tid] += sd2[tid + off]; }
        __syncthreads();
    }
    if (tid == 0) {
        double m   = sd[0]  / (double)NHW;
        double var = sd2[0] / (double)NHW - m * m;
        double inv = 1.0 / sqrt(var + 1e-5);
        double A   = (double)g1[0] * inv;
        g_bn1AB[0] = (float)A;
        g_bn1AB[1] = (float)((double)be1[0] - m * A);
    }
}

// ================= K3: BN1 apply + fuzzify =====================================
__global__ __launch_bounds__(256) void k3_fuzz(const float* __restrict__ lb,
                                               const float* __restrict__ ub) {
    int i = blockIdx.x * 256 + threadIdx.x;  // 1 float4 per thread; grid 1024
    float A = g_bn1AB[0], B = g_bn1AB[1];
    float Ls[4], Us[4];
    #pragma unroll
    for (int f = 0; f < 4; ++f) { Ls[f] = __ldg(lb + f); Us[f] = __ldg(ub + f); }

    float4 h4 = ((const float4*)g_h)[i];
    float hv[4] = {h4.x, h4.y, h4.z, h4.w};
    float ov[4];
    #pragma unroll
    for (int e = 0; e < 4; ++e) {
        float xv = hv[e] * A + B;
        float fz = 0.f;
        #pragma unroll
        for (int f = 0; f < 4; ++f) {
            float lbv = Ls[f], ubv = Us[f];
            float ld = xv - lbv, ud = ubv - xv;
            bool inr  = (ld > 0.f) && (ud > 0.f);
            bool outr = (ld < 0.f) || (ud < 0.f);
            float e1 = __expf(-0.5f * ld * ld);
            float a2 = inr ? ud : (ud + 2.f * ld);      // ub - x_ref when reflected
            float e2 = __expf(-0.5f * a2 * a2);
            float c  = (inr || outr) ? (e1 + e2) : 0.f;
            fz += c;
            if (outr) xv = 2.f * lbv - xv;
        }
        ov[e] = fz;
    }
    ((float4*)g_fz)[i] = make_float4(ov[0], ov[1], ov[2], ov[3]);
}

// ================= K4: neighborhood sums v[9] + Gram M[45] of fz ================
// grid (16 rowgroups of 16, 16 n), 256 threads = one column each.
__global__ __launch_bounds__(256) void k4_stats() {
    __shared__ float sm[18][258];
    __shared__ float red[8][54];
    int tid = threadIdx.x;
    int rg = blockIdx.x, n = blockIdx.y;

    for (int i = tid; i < 18 * 258; i += 256) (&sm[0][0])[i] = 0.f;
    __syncthreads();
    const float* base = g_fz + (size_t)n * HW;
    #pragma unroll
    for (int r = 0; r < 18; ++r) {
        int gr = rg * 16 - 1 + r;
        if (gr >= 0 && gr < Hh) sm[r][tid + 1] = base[gr * Ww + tid];
    }
    __syncthreads();

    float v[9], M[45];
    #pragma unroll
    for (int i = 0; i < 9; ++i) v[i] = 0.f;
    #pragma unroll
    for (int i = 0; i < 45; ++i) M[i] = 0.f;

    #pragma unroll
    for (int o = 0; o < 16; ++o) {
        float f[9];
        #pragma unroll
        for (int kh = 0; kh < 3; ++kh)
            #pragma unroll
            for (int kw = 0; kw < 3; ++kw)
                f[kh * 3 + kw] = sm[o + kh][tid + kw];
        int k = 0;
        #pragma unroll
        for (int i = 0; i < 9; ++i) {
            v[i] += f[i];
            #pragma unroll
            for (int j = i; j < 9; ++j) M[k++] += f[i] * f[j];
        }
    }

    int wid = tid >> 5, lane = tid & 31;
    #pragma unroll
    for (int q = 0; q < 54; ++q) {
        float t = (q < 9) ? v[q] : M[q - 9];
        #pragma unroll
        for (int off = 16; off; off >>= 1) t += __shfl_down_sync(0xffffffffu, t, off);
        if (lane == 0) red[wid][q] = t;
    }
    __syncthreads();
    if (tid < 54) {
        float t = 0.f;
        #pragma unroll
        for (int u = 0; u < 8; ++u) t += red[u][tid];
        g_part2[(n * 16 + rg) * 54 + tid] = t;
    }
}

// ================= K4b: per-channel BN2 stats via v/M -> fused weights ==========
__global__ __launch_bounds__(64) void k4b_fuse(const float* __restrict__ w2,
                                               const float* __restrict__ b2,
                                               const float* __restrict__ g2,
                                               const float* __restrict__ be2) {
    __shared__ double S[54];
    int tid = threadIdx.x;
    if (tid < 54) {
        double t = 0.0;
        for (int b = 0; b < 256; ++b) t += (double)g_part2[b * 54 + tid];
        S[tid] = t;
    }
    __syncthreads();

    int c = tid;
    double w[9];
    #pragma unroll
    for (int j = 0; j < 9; ++j) w[j] = (double)w2[c * 9 + j];
    double bb = (double)b2[c];

    double dot = 0.0;
    #pragma unroll
    for (int j = 0; j < 9; ++j) dot += w[j] * S[j];
    double S2 = 0.0;
    int k = 9;
    #pragma unroll
    for (int i = 0; i < 9; ++i)
        #pragma unroll
        for (int j = i; j < 9; ++j) {
            double m = S[k++];
            S2 += (i == j) ? w[i] * w[i] * m : 2.0 * w[i] * w[j] * m;
        }

    double S1   = dot + bb * (double)NHW;
    double sq   = S2 + 2.0 * bb * dot + bb * bb * (double)NHW;
    double mean = S1 / (double)NHW;
    double var  = sq / (double)NHW - mean * mean;
    double inv  = 1.0 / sqrt(var + 1e-5);
    double A    = (double)g2[c] * inv;
    double B    = (double)be2[c] - mean * A;
    #pragma unroll
    for (int j = 0; j < 9; ++j) g_Wf[c * 10 + j] = (float)(w[j] * A);
    g_Wf[c * 10 + 9] = (float)(bb * A + B);
}

// ================= K5: conv2 (1ch -> 64ch) with fused BN2, write output =========
// grid (16 rowgroups of 16, 16 n); 256 threads: 64 in w (4 cols each) x 4 in h (4 rows each)
__global__ __launch_bounds__(256) void k5_conv2(float* __restrict__ out) {
    __shared__ float swf[640];
    int tid = threadIdx.x;
    int rg = blockIdx.x, n = blockIdx.y;
    for (int i = tid; i < 640; i += 256) swf[i] = g_Wf[i];
    __syncthreads();

    int wt = tid & 63, ht = tid >> 6;
    int wq = wt * 4, gr0 = rg * 16 + ht * 4;
    const float* base = g_fz + (size_t)n * HW;

    float win[6][6];
    #pragma unroll
    for (int rr = 0; rr < 6; ++rr) {
        int gr = gr0 - 1 + rr;
        bool rok = (gr >= 0 && gr < Hh);
        #pragma unroll
        for (int cc = 0; cc < 6; ++cc) {
            int gc = wq - 1 + cc;
            bool ok = rok && (gc >= 0) && (gc < Ww);
            win[rr][cc] = ok ? __ldg(base + gr * Ww + gc) : 0.f;
        }
    }

    size_t obase = (size_t)n * Cc * HW + (size_t)gr0 * Ww + wq;
    for (int c = 0; c < 64; ++c) {
        float wc[10];
        #pragma unroll
        for (int j = 0; j < 10; ++j) wc[j] = swf[c * 10 + j];
        #pragma unroll
        for (int a = 0; a < 4; ++a) {
            float y[4];
            #pragma unroll
            for (int b = 0; b < 4; ++b) {
                float acc = wc[9];
                #pragma unroll
                for (int kh = 0; kh < 3; ++kh)
                    #pragma unroll
                    for (int kw = 0; kw < 3; ++kw)
                        acc = fmaf(wc[kh * 3 + kw], win[a + kh][b + kw], acc);
                y[b] = acc;
            }
            *(float4*)(out + obase + (size_t)c * HW + (size_t)a * Ww) =
                make_float4(y[0], y[1], y[2], y[3]);
        }
    }
}

// ================= launch =======================================================
extern "C" void kernel_launch(void* const* d_in, const int* in_sizes, int n_in,
                              void* d_out, int out_size) {
    const float* x   = (const float*)d_in[0];
    const float* w1  = (const float*)d_in[1];
    const float* b1  = (const float*)d_in[2];
    const float* w2  = (const float*)d_in[3];
    const float* b2  = (const float*)d_in[4];
    const float* g1  = (const float*)d_in[5];
    const float* be1 = (const float*)d_in[6];
    const float* g2  = (const float*)d_in[7];
    const float* be2 = (const float*)d_in[8];
    const float* lb  = (const float*)d_in[9];
    const float* ub  = (const float*)d_in[10];
    float* out = (float*)d_out;

    k1_conv1<<<dim3(32, 16), 128>>>(x, w1, b1);
    k2_bn1<<<1, 256>>>(g1, be1);
    k3_fuzz<<<1024, 256>>>(lb, ub);
    k4_stats<<<dim3(16, 16), 256>>>();
    k4b_fuse<<<1, 64>>>(w2, b2, g2, be2);
    k5_conv2<<<dim3(16, 16), 256>>>(out);
}